// round 3
// baseline (speedup 1.0000x reference)
#include <cuda_runtime.h>
#include <math.h>

#define NN    8192
#define DINN  256
#define DOUTT 128
#define LALPHA 0.2f
#define MAXK  128

// ---------------- scratch (no allocation allowed) ----------------
__device__ __align__(16) float g_h[NN * DOUTT];     // h = input @ W
__device__ __align__(16) float g_s[NN];             // h @ a_self
__device__ __align__(16) float g_t[NN];             // h @ a_neighs
__device__ __align__(16) float g_E[2 * NN];         // interleaved {E1=e^t, E2=e^(a*t)}
__device__ __align__(16) float g_tsorted[NN];       // t sorted descending
__device__ __align__(16) int   g_perm[NN];          // perm[rank] = j

// ---------------- h = input @ W  (M=8192, K=256, N=128) ----------------
__global__ __launch_bounds__(256) void k_gemm(const float* __restrict__ X,
                                              const float* __restrict__ W) {
    __shared__ float As[64][64];    // 16 KB
    __shared__ float Bs[64][128];   // 32 KB
    int tid = threadIdx.x;
    int m0  = blockIdx.x * 64;
    int tr  = tid >> 5;     // 0..7 -> rows tr*8..tr*8+7
    int tc  = tid & 31;     // 0..31 -> cols tc*4..tc*4+3

    float acc[8][4];
#pragma unroll
    for (int r = 0; r < 8; r++)
#pragma unroll
        for (int c = 0; c < 4; c++) acc[r][c] = 0.f;

    for (int k0 = 0; k0 < DINN; k0 += 64) {
#pragma unroll
        for (int l = 0; l < 4; l++) {
            int lin = l * 1024 + tid * 4;
            int r = lin >> 6, k = lin & 63;
            float4 v = *(const float4*)(X + (size_t)(m0 + r) * DINN + k0 + k);
            *(float4*)&As[r][k] = v;
        }
#pragma unroll
        for (int l = 0; l < 8; l++) {
            int lin = l * 1024 + tid * 4;
            int kk = lin >> 7, n = lin & 127;
            float4 v = *(const float4*)(W + (size_t)(k0 + kk) * DOUTT + n);
            *(float4*)&Bs[kk][n] = v;
        }
        __syncthreads();
#pragma unroll 4
        for (int kk = 0; kk < 64; ++kk) {
            float4 b = *(const float4*)&Bs[kk][tc * 4];
#pragma unroll
            for (int r = 0; r < 8; r++) {
                float a = As[tr * 8 + r][kk];
                acc[r][0] += a * b.x;
                acc[r][1] += a * b.y;
                acc[r][2] += a * b.z;
                acc[r][3] += a * b.w;
            }
        }
        __syncthreads();
    }
#pragma unroll
    for (int r = 0; r < 8; r++) {
        float4 v = make_float4(acc[r][0], acc[r][1], acc[r][2], acc[r][3]);
        *(float4*)(g_h + (size_t)(m0 + tr * 8 + r) * DOUTT + tc * 4) = v;
    }
}

// ---------------- s, t, E1, E2 per row ----------------
__global__ __launch_bounds__(256) void k_stats(const float* __restrict__ a_self,
                                               const float* __restrict__ a_neighs) {
    int warp = threadIdx.x >> 5, lane = threadIdx.x & 31;
    int row = blockIdx.x * 8 + warp;
    float4 h  = ((const float4*)(g_h + (size_t)row * DOUTT))[lane];
    float4 as = ((const float4*)a_self)[lane];
    float4 an = ((const float4*)a_neighs)[lane];
    float s = h.x * as.x + h.y * as.y + h.z * as.z + h.w * as.w;
    float t = h.x * an.x + h.y * an.y + h.z * an.z + h.w * an.w;
#pragma unroll
    for (int o = 16; o; o >>= 1) {
        s += __shfl_xor_sync(0xffffffffu, s, o);
        t += __shfl_xor_sync(0xffffffffu, t, o);
    }
    if (lane == 0) {
        g_s[row] = s;
        g_t[row] = t;
        g_E[2 * row]     = __expf(t);
        g_E[2 * row + 1] = __expf(LALPHA * t);
    }
}

// ---------------- global descending rank sort of t (stable, exact) ----------------
// rank(j) = #{ k : t[k] > t[j]  ||  (t[k]==t[j] && k<j) }  -> permutation
__global__ __launch_bounds__(256) void k_rank() {
    __shared__ float ts[NN];        // 32 KB
    __shared__ int   partial[256];
    int tid = threadIdx.x;
#pragma unroll
    for (int l = 0; l < 8; l++) {
        int lin = l * 1024 + tid * 4;
        *(float4*)&ts[lin] = *(const float4*)(g_t + lin);
    }
    __syncthreads();

    int local = tid >> 2;             // 0..63 : which j within this block
    int q     = tid & 3;              // quarter of the count loop
    int j     = blockIdx.x * 64 + local;
    float tj  = ts[j];
    int cnt = 0;
    int k0 = q * 2048;
#pragma unroll 8
    for (int k = k0; k < k0 + 2048; ++k) {
        float tk = ts[k];
        cnt += (tk > tj) || (tk == tj && k < j);
    }
    partial[tid] = cnt;
    __syncthreads();
    if (q == 0) {
        int rank = partial[tid] + partial[tid + 1] + partial[tid + 2] + partial[tid + 3];
        g_perm[rank]    = j;
        g_tsorted[rank] = tj;
    }
}

// ---------------- main fused row kernel ----------------
// per row i:
//   denom   = A * sum_{valid, t>=-s} E1 + B * sum_{valid, t<-s} E2,  A=e^{s-M}, B=e^{a*s-M}
//   t_thr   = (action[i])-th largest valid t  (walk global sorted order + adj bitmask)
//   h_prime = sum over kept (valid & t>=t_thr) of (numerator/denom) * h[j]
//   out     = elu(h_prime)
__global__ __launch_bounds__(256) void k_row(const int* __restrict__ adj,
                                             const int* __restrict__ action,
                                             const int* __restrict__ bp,
                                             float* __restrict__ out) {
    __shared__ unsigned char s_nib[2048];   // adj row as bits: 4 bits/thread/iter
    __shared__ float s_red[24];
    __shared__ float s_par[4];              // A, B, denom
    __shared__ int   s_info[2];             // kept count, fallback flag
    __shared__ int   s_klist[MAXK];
    __shared__ float s_wlist[MAXK];
    __shared__ float s_acc[DOUTT];

    int row = blockIdx.x;
    int tid = threadIdx.x;
    int lane = tid & 31, warp = tid >> 5;

    float s_i  = g_s[row];
    float cthr = __expf(-s_i);              // E1 >= cthr  <=>  t >= -s_i
    const int* arow = adj + (size_t)row * NN;

    float sum1 = 0.f, sum2 = 0.f, emax = 0.f;   // E1 > 0, so 0 == "no valid"
#pragma unroll
    for (int it = 0; it < 8; ++it) {
        int base = it * 1024 + tid * 4;
        int4 av   = *(const int4*)(arow + base);
        float4 eA = __ldg((const float4*)(g_E + 2 * base));       // E1,E2 of j0,j1
        float4 eB = __ldg((const float4*)(g_E + 2 * base + 4));   // E1,E2 of j2,j3
        unsigned nb = 0;
        if (av.x > 0) { nb |= 1u; float e1 = eA.x; emax = fmaxf(emax, e1); if (e1 >= cthr) sum1 += e1; else sum2 += eA.y; }
        if (av.y > 0) { nb |= 2u; float e1 = eA.z; emax = fmaxf(emax, e1); if (e1 >= cthr) sum1 += e1; else sum2 += eA.w; }
        if (av.z > 0) { nb |= 4u; float e1 = eB.x; emax = fmaxf(emax, e1); if (e1 >= cthr) sum1 += e1; else sum2 += eB.y; }
        if (av.w > 0) { nb |= 8u; float e1 = eB.z; emax = fmaxf(emax, e1); if (e1 >= cthr) sum1 += e1; else sum2 += eB.w; }
        s_nib[it * 256 + tid] = (unsigned char)nb;
    }
#pragma unroll
    for (int o = 16; o; o >>= 1) {
        sum1 += __shfl_xor_sync(0xffffffffu, sum1, o);
        sum2 += __shfl_xor_sync(0xffffffffu, sum2, o);
        emax = fmaxf(emax, __shfl_xor_sync(0xffffffffu, emax, o));
    }
    if (lane == 0) { s_red[warp] = sum1; s_red[8 + warp] = sum2; s_red[16 + warp] = emax; }
    __syncthreads();

    if (warp == 0) {
        float S1 = (lane < 8) ? s_red[lane] : 0.f;
        float S2 = (lane < 8) ? s_red[8 + lane] : 0.f;
        float EM = (lane < 8) ? s_red[16 + lane] : 0.f;
#pragma unroll
        for (int o = 4; o; o >>= 1) {
            S1 += __shfl_xor_sync(0xffffffffu, S1, o);
            S2 += __shfl_xor_sync(0xffffffffu, S2, o);
            EM = fmaxf(EM, __shfl_xor_sync(0xffffffffu, EM, o));
        }
        S1 = __shfl_sync(0xffffffffu, S1, 0);
        S2 = __shfl_sync(0xffffffffu, S2, 0);
        EM = __shfl_sync(0xffffffffu, EM, 0);

        float tmax = __logf(EM);                      // max valid t (M only stabilizes, errors cancel)
        float x = s_i + tmax;
        float M = (x >= 0.f) ? x : LALPHA * x;
        float A = __expf(s_i - M);
        float B = __expf(LALPHA * s_i - M);
        float denom = A * S1 + B * S2;
        if (lane == 0) { s_par[0] = A; s_par[1] = B; s_par[2] = denom; }

        int fallback = 0;
        int c2 = 0;
        if (bp[0] != 0) {
            int target = action[row] + 1;       // keep `target` entries (plus exact ties)
            // Phase A: find threshold t value = target-th largest valid t
            int cnt = 0, pos = 0, found = 0;
            float t_thr = 0.f;
            while (pos < NN) {
                int r = pos + lane;
                int j = g_perm[r];
                float tv = g_tsorted[r];
                int bit = (s_nib[((j >> 10) << 8) + ((j >> 2) & 255)] >> (j & 3)) & 1;
                unsigned bal = __ballot_sync(0xffffffffu, bit);
                int c = __popc(bal);
                if (cnt + c >= target) {
                    int prefx = __popc(bal & ((1u << lane) - 1));
                    int sel = bit && (cnt + prefx + 1 == target);
                    unsigned sm = __ballot_sync(0xffffffffu, sel);
                    int src = __ffs(sm) - 1;
                    t_thr = __shfl_sync(0xffffffffu, tv, src);
                    found = 1;
                    break;
                }
                cnt += c;
                pos += 32;
            }
            if (!found) fallback = 1;   // fewer valid than target -> ref threshold is 0 -> keep all valid

            // Phase B: collect kept (valid & t >= t_thr) with weights
            if (!fallback) {
                float A0 = s_par[0]; // same regs, just reuse
                pos = 0;
                while (pos < NN) {
                    int r = pos + lane;
                    float tv = g_tsorted[r];
                    int j = g_perm[r];
                    int bit = (s_nib[((j >> 10) << 8) + ((j >> 2) & 255)] >> (j & 3)) & 1;
                    bool ge = (tv >= t_thr);
                    bool keep = bit && ge;
                    unsigned balk = __ballot_sync(0xffffffffu, keep);
                    int idx = c2 + __popc(balk & ((1u << lane) - 1));
                    if (keep && idx < MAXK) {
                        float e1 = __ldg(&g_E[2 * j]);
                        float e2 = __ldg(&g_E[2 * j + 1]);
                        float w = (e1 >= cthr) ? A0 * e1 : B * e2;
                        s_klist[idx] = j;
                        s_wlist[idx] = w / denom;
                    }
                    c2 += __popc(balk);
                    if (c2 > MAXK) break;                               // tie explosion -> fallback
                    if (__ballot_sync(0xffffffffu, ge) != 0xffffffffu) break;  // sorted: done
                    pos += 32;
                }
                if (c2 > MAXK) fallback = 1;
            }
        } else {
            fallback = 1;   // no thresholding: dense path over all valid
        }
        if (lane == 0) { s_info[0] = c2; s_info[1] = fallback; }
    }
    __syncthreads();

    int c2 = s_info[0];
    int fb = s_info[1];
    float A = s_par[0], B = s_par[1], denom = s_par[2];
    int d = tid & 127, half = tid >> 7;
    float acc = 0.f;
    if (!fb) {
        for (int k = half; k < c2; k += 2)
            acc += s_wlist[k] * g_h[(size_t)s_klist[k] * DOUTT + d];
    } else {
        float inv = 1.f / denom;
        int j0 = half * (NN / 2);
        for (int j = j0; j < j0 + NN / 2; ++j) {
            int bit = (s_nib[((j >> 10) << 8) + ((j >> 2) & 255)] >> (j & 3)) & 1;
            if (bit) {
                float e1 = __ldg(&g_E[2 * j]);
                float e2 = __ldg(&g_E[2 * j + 1]);
                float w = ((e1 >= cthr) ? A * e1 : B * e2) * inv;
                acc += w * g_h[(size_t)j * DOUTT + d];
            }
        }
    }
    if (half) s_acc[d] = acc;
    __syncthreads();
    if (!half) {
        float v = acc + s_acc[d];
        out[(size_t)row * DOUTT + d] = (v > 0.f) ? v : expm1f(v);
    }
}

// ---------------- launch ----------------
extern "C" void kernel_launch(void* const* d_in, const int* in_sizes, int n_in,
                              void* d_out, int out_size) {
    const float* input    = (const float*)d_in[0];
    const int*   adj      = (const int*)d_in[1];
    const int*   action   = (const int*)d_in[2];
    const float* W        = (const float*)d_in[3];
    const float* a_self   = (const float*)d_in[4];
    const float* a_neighs = (const float*)d_in[5];
    const int*   bp       = (const int*)d_in[6];
    float* out = (float*)d_out;

    k_gemm<<<NN / 64, 256>>>(input, W);
    k_stats<<<NN / 8, 256>>>(a_self, a_neighs);
    k_rank<<<NN / 64, 256>>>();
    k_row<<<NN, 256>>>(adj, action, bp, out);
}

// round 4
// speedup vs baseline: 1.4823x; 1.4823x over previous
#include <cuda_runtime.h>
#include <math.h>

#define NN    8192
#define DINN  256
#define DOUTT 128
#define LALPHA 0.2f
#define MAXK  128

// ---------------- scratch (no allocation allowed) ----------------
__device__ __align__(16) float g_h[NN * DOUTT];     // h = input @ W
__device__ __align__(16) float g_s[NN];             // h @ a_self
__device__ __align__(16) float g_t[NN];             // h @ a_neighs
__device__ __align__(16) float g_E[2 * NN];         // interleaved {E1=e^t, E2=e^(a*t)}
__device__ __align__(16) float g_tsorted[NN];       // t sorted descending
__device__ __align__(16) int   g_perm[NN];          // perm[rank] = j

// packed fp32x2 helpers (FFMA2 path — PTX-only per sm_103a SASS notes)
__device__ __forceinline__ unsigned long long pack2(float lo, float hi) {
    unsigned long long r;
    asm("mov.b64 %0, {%1, %2};" : "=l"(r) : "r"(__float_as_uint(lo)), "r"(__float_as_uint(hi)));
    return r;
}
__device__ __forceinline__ void unpack2(unsigned long long v, float& lo, float& hi) {
    unsigned a, b;
    asm("mov.b64 {%0, %1}, %2;" : "=r"(a), "=r"(b) : "l"(v));
    lo = __uint_as_float(a); hi = __uint_as_float(b);
}
__device__ __forceinline__ unsigned long long ffma2(unsigned long long a, unsigned long long b,
                                                    unsigned long long c) {
    unsigned long long d;
    asm("fma.rn.f32x2 %0, %1, %2, %3;" : "=l"(d) : "l"(a), "l"(b), "l"(c));
    return d;
}

// ---------------- h = input @ W  (M=8192, K=256, N=128) + fused stats ----------------
__global__ __launch_bounds__(256) void k_gemm(const float* __restrict__ X,
                                              const float* __restrict__ W,
                                              const float* __restrict__ a_self,
                                              const float* __restrict__ a_neighs) {
    __shared__ float As[64][64];    // 16 KB
    __shared__ float Bs[64][128];   // 32 KB
    int tid = threadIdx.x;
    int m0  = blockIdx.x * 64;
    int tr  = tid >> 5;     // warp id -> rows tr*8..tr*8+7
    int tc  = tid & 31;     // lane -> cols tc*4..tc*4+3

    unsigned long long acc01[8], acc23[8];
#pragma unroll
    for (int r = 0; r < 8; r++) { acc01[r] = 0ull; acc23[r] = 0ull; }

    for (int k0 = 0; k0 < DINN; k0 += 64) {
#pragma unroll
        for (int l = 0; l < 4; l++) {
            int lin = l * 1024 + tid * 4;
            int r = lin >> 6, k = lin & 63;
            float4 v = *(const float4*)(X + (size_t)(m0 + r) * DINN + k0 + k);
            *(float4*)&As[r][k] = v;
        }
#pragma unroll
        for (int l = 0; l < 8; l++) {
            int lin = l * 1024 + tid * 4;
            int kk = lin >> 7, n = lin & 127;
            float4 v = *(const float4*)(W + (size_t)(k0 + kk) * DOUTT + n);
            *(float4*)&Bs[kk][n] = v;
        }
        __syncthreads();
#pragma unroll 4
        for (int kk = 0; kk < 64; ++kk) {
            float4 b = *(const float4*)&Bs[kk][tc * 4];
            unsigned long long b01 = pack2(b.x, b.y);
            unsigned long long b23 = pack2(b.z, b.w);
#pragma unroll
            for (int r = 0; r < 8; r++) {
                float a = As[tr * 8 + r][kk];
                unsigned long long aa = pack2(a, a);
                acc01[r] = ffma2(aa, b01, acc01[r]);
                acc23[r] = ffma2(aa, b23, acc23[r]);
            }
        }
        __syncthreads();
    }

    // epilogue: store h and fused per-row stats (s, t, E1, E2)
    float4 as4 = ((const float4*)a_self)[tc];
    float4 an4 = ((const float4*)a_neighs)[tc];
#pragma unroll
    for (int r = 0; r < 8; r++) {
        float4 v;
        unpack2(acc01[r], v.x, v.y);
        unpack2(acc23[r], v.z, v.w);
        int row = m0 + tr * 8 + r;
        *(float4*)(g_h + (size_t)row * DOUTT + tc * 4) = v;

        float s = v.x * as4.x + v.y * as4.y + v.z * as4.z + v.w * as4.w;
        float t = v.x * an4.x + v.y * an4.y + v.z * an4.z + v.w * an4.w;
#pragma unroll
        for (int o = 16; o; o >>= 1) {
            s += __shfl_xor_sync(0xffffffffu, s, o);
            t += __shfl_xor_sync(0xffffffffu, t, o);
        }
        if (tc == 0) {
            g_s[row] = s;
            g_t[row] = t;
            g_E[2 * row]     = __expf(t);
            g_E[2 * row + 1] = __expf(LALPHA * t);
        }
    }
}

// ---------------- global descending rank sort of t (stable, exact) ----------------
__global__ __launch_bounds__(256) void k_rank() {
    __shared__ float ts[NN];        // 32 KB
    __shared__ int   partial[256];
    int tid = threadIdx.x;
#pragma unroll
    for (int l = 0; l < 8; l++) {
        int lin = l * 1024 + tid * 4;
        *(float4*)&ts[lin] = *(const float4*)(g_t + lin);
    }
    __syncthreads();

    int local = tid >> 2;
    int q     = tid & 3;
    int j     = blockIdx.x * 64 + local;
    float tj  = ts[j];
    int cnt = 0;
    int k0 = q * 2048;
#pragma unroll 8
    for (int k = k0; k < k0 + 2048; ++k) {
        float tk = ts[k];
        cnt += (tk > tj) || (tk == tj && k < j);
    }
    partial[tid] = cnt;
    __syncthreads();
    if (q == 0) {
        int rank = partial[tid] + partial[tid + 1] + partial[tid + 2] + partial[tid + 3];
        g_perm[rank]    = j;
        g_tsorted[rank] = tj;
    }
}

// ---------------- main fused row kernel (branch-free hot loop) ----------------
__global__ __launch_bounds__(256) void k_row(const int* __restrict__ adj,
                                             const int* __restrict__ action,
                                             const int* __restrict__ bp,
                                             float* __restrict__ out) {
    __shared__ float s_red[16];
    __shared__ float s_par[3];              // A, B, denom
    __shared__ int   s_info[2];             // kept count, fallback flag
    __shared__ int   s_klist[MAXK];
    __shared__ float s_wlist[MAXK];
    __shared__ float s_acc[DOUTT];

    int row = blockIdx.x;
    int tid = threadIdx.x;
    int lane = tid & 31, warp = tid >> 5;

    float s_i  = g_s[row];
    float cthr = __expf(-s_i);              // E1 >= cthr  <=>  t >= -s_i
    const int* arow = adj + (size_t)row * NN;

    float sum1 = 0.f, sum2 = 0.f;
#pragma unroll
    for (int it = 0; it < 8; ++it) {
        int base = it * 1024 + tid * 4;
        int4 av   = __ldcs((const int4*)(arow + base));               // streaming, evict-first
        float4 eA = __ldg((const float4*)(g_E + 2 * base));           // {E1,E2} of j0,j1
        float4 eB = __ldg((const float4*)(g_E + 2 * base + 4));       // {E1,E2} of j2,j3
        bool v0 = av.x > 0, v1 = av.y > 0, v2 = av.z > 0, v3 = av.w > 0;
        sum1 += (v0 && eA.x >= cthr) ? eA.x : 0.f;
        sum2 += (v0 && eA.x <  cthr) ? eA.y : 0.f;
        sum1 += (v1 && eA.z >= cthr) ? eA.z : 0.f;
        sum2 += (v1 && eA.z <  cthr) ? eA.w : 0.f;
        sum1 += (v2 && eB.x >= cthr) ? eB.x : 0.f;
        sum2 += (v2 && eB.x <  cthr) ? eB.y : 0.f;
        sum1 += (v3 && eB.z >= cthr) ? eB.z : 0.f;
        sum2 += (v3 && eB.z <  cthr) ? eB.w : 0.f;
    }
#pragma unroll
    for (int o = 16; o; o >>= 1) {
        sum1 += __shfl_xor_sync(0xffffffffu, sum1, o);
        sum2 += __shfl_xor_sync(0xffffffffu, sum2, o);
    }
    if (lane == 0) { s_red[warp] = sum1; s_red[8 + warp] = sum2; }
    __syncthreads();

    if (warp == 0) {
        float S1 = (lane < 8) ? s_red[lane] : 0.f;
        float S2 = (lane < 8) ? s_red[8 + lane] : 0.f;
#pragma unroll
        for (int o = 4; o; o >>= 1) {
            S1 += __shfl_xor_sync(0xffffffffu, S1, o);
            S2 += __shfl_xor_sync(0xffffffffu, S2, o);
        }
        S1 = __shfl_sync(0xffffffffu, S1, 0);
        S2 = __shfl_sync(0xffffffffu, S2, 0);

        // unstabilized softmax: magnitudes bounded (|s+t| <~ 30), safe in fp32
        float A = __expf(s_i);
        float B = __expf(LALPHA * s_i);
        float denom = A * S1 + B * S2;
        if (lane == 0) { s_par[0] = A; s_par[1] = B; s_par[2] = denom; }

        int fallback = 0;
        int c2 = 0;
        if (bp[0] != 0) {
            int target = action[row] + 1;       // keep `target` entries (plus exact ties)
            // Phase A: threshold t value = target-th largest valid t (sorted walk + adj gather)
            int cnt = 0, pos = 0, found = 0;
            float t_thr = 0.f;
            while (pos < NN) {
                int r = pos + lane;
                int j = g_perm[r];
                float tv = g_tsorted[r];
                int bit = __ldg(arow + j) > 0;
                unsigned bal = __ballot_sync(0xffffffffu, bit);
                int c = __popc(bal);
                if (cnt + c >= target) {
                    int prefx = __popc(bal & ((1u << lane) - 1));
                    int sel = bit && (cnt + prefx + 1 == target);
                    unsigned sm = __ballot_sync(0xffffffffu, sel);
                    int src = __ffs(sm) - 1;
                    t_thr = __shfl_sync(0xffffffffu, tv, src);
                    found = 1;
                    break;
                }
                cnt += c;
                pos += 32;
            }
            if (!found) fallback = 1;   // fewer valid than target -> threshold 0 -> keep all valid

            // Phase B: collect kept (valid & t >= t_thr) with weights
            if (!fallback) {
                pos = 0;
                while (pos < NN) {
                    int r = pos + lane;
                    float tv = g_tsorted[r];
                    int j = g_perm[r];
                    int bit = __ldg(arow + j) > 0;
                    bool ge = (tv >= t_thr);
                    bool keep = bit && ge;
                    unsigned balk = __ballot_sync(0xffffffffu, keep);
                    int idx = c2 + __popc(balk & ((1u << lane) - 1));
                    if (keep && idx < MAXK) {
                        float e1 = __ldg(&g_E[2 * j]);
                        float e2 = __ldg(&g_E[2 * j + 1]);
                        float w = (e1 >= cthr) ? A * e1 : B * e2;
                        s_klist[idx] = j;
                        s_wlist[idx] = w / denom;
                    }
                    c2 += __popc(balk);
                    if (c2 > MAXK) break;                                      // tie explosion
                    if (__ballot_sync(0xffffffffu, ge) != 0xffffffffu) break;  // sorted: done
                    pos += 32;
                }
                if (c2 > MAXK) fallback = 1;
            }
        } else {
            fallback = 1;   // no thresholding: dense path over all valid
        }
        if (lane == 0) { s_info[0] = c2; s_info[1] = fallback; }
    }
    __syncthreads();

    int c2 = s_info[0];
    int fb = s_info[1];
    float A = s_par[0], B = s_par[1], denom = s_par[2];
    int d = tid & 127, half = tid >> 7;
    float acc = 0.f;
    if (!fb) {
        for (int k = half; k < c2; k += 2)
            acc += s_wlist[k] * g_h[(size_t)s_klist[k] * DOUTT + d];
    } else {
        float inv = 1.f / denom;
        int j0 = half * (NN / 2);
        for (int j = j0; j < j0 + NN / 2; ++j) {
            if (__ldg(arow + j) > 0) {
                float e1 = __ldg(&g_E[2 * j]);
                float e2 = __ldg(&g_E[2 * j + 1]);
                float w = ((e1 >= cthr) ? A * e1 : B * e2) * inv;
                acc += w * g_h[(size_t)j * DOUTT + d];
            }
        }
    }
    if (half) s_acc[d] = acc;
    __syncthreads();
    if (!half) {
        float v = acc + s_acc[d];
        out[(size_t)row * DOUTT + d] = (v > 0.f) ? v : expm1f(v);
    }
}

// ---------------- launch ----------------
extern "C" void kernel_launch(void* const* d_in, const int* in_sizes, int n_in,
                              void* d_out, int out_size) {
    const float* input    = (const float*)d_in[0];
    const int*   adj      = (const int*)d_in[1];
    const int*   action   = (const int*)d_in[2];
    const float* W        = (const float*)d_in[3];
    const float* a_self   = (const float*)d_in[4];
    const float* a_neighs = (const float*)d_in[5];
    const int*   bp       = (const int*)d_in[6];
    float* out = (float*)d_out;

    k_gemm<<<NN / 64, 256>>>(input, W, a_self, a_neighs);
    k_rank<<<NN / 64, 256>>>();
    k_row<<<NN, 256>>>(adj, action, bp, out);
}

// round 5
// speedup vs baseline: 1.8276x; 1.2329x over previous
#include <cuda_runtime.h>
#include <math.h>

#define NN    8192
#define DINN  256
#define DOUTT 128
#define LALPHA 0.2f
#define MAXK  128
#define RPB   2          // rows per block in k_row

// ---------------- scratch (no allocation allowed) ----------------
__device__ __align__(16) float g_h[NN * DOUTT];     // h = input @ W
__device__ __align__(16) float g_s[NN];             // h @ a_self
__device__ __align__(16) float g_t[NN];             // h @ a_neighs
__device__ __align__(16) float g_E[2 * NN];         // interleaved {E1=e^t, E2=e^(a*t)}
__device__ __align__(16) float g_tsorted[NN];       // t sorted descending
__device__ __align__(16) int   g_perm[NN];          // perm[rank] = j

// packed fp32x2 helpers (FFMA2 path — PTX-only per sm_103a SASS notes)
__device__ __forceinline__ unsigned long long pack2(float lo, float hi) {
    unsigned long long r;
    asm("mov.b64 %0, {%1, %2};" : "=l"(r) : "r"(__float_as_uint(lo)), "r"(__float_as_uint(hi)));
    return r;
}
__device__ __forceinline__ void unpack2(unsigned long long v, float& lo, float& hi) {
    unsigned a, b;
    asm("mov.b64 {%0, %1}, %2;" : "=r"(a), "=r"(b) : "l"(v));
    lo = __uint_as_float(a); hi = __uint_as_float(b);
}
__device__ __forceinline__ unsigned long long ffma2(unsigned long long a, unsigned long long b,
                                                    unsigned long long c) {
    unsigned long long d;
    asm("fma.rn.f32x2 %0, %1, %2, %3;" : "=l"(d) : "l"(a), "l"(b), "l"(c));
    return d;
}

// ---------------- h = input @ W  (M=8192, K=256, N=128) + fused stats ----------------
// M-tile = 32 rows/block -> grid 256 (>=148 SMs), smem 40KB.
__global__ __launch_bounds__(256) void k_gemm(const float* __restrict__ X,
                                              const float* __restrict__ W,
                                              const float* __restrict__ a_self,
                                              const float* __restrict__ a_neighs) {
    __shared__ float As[32][64];    // 8 KB
    __shared__ float Bs[64][128];   // 32 KB
    int tid  = threadIdx.x;
    int m0   = blockIdx.x * 32;
    int warp = tid >> 5;            // 8 warps -> rows warp*4..warp*4+3
    int lane = tid & 31;            // cols lane*4..lane*4+3

    unsigned long long acc01[4], acc23[4];
#pragma unroll
    for (int r = 0; r < 4; r++) { acc01[r] = 0ull; acc23[r] = 0ull; }

    for (int k0 = 0; k0 < DINN; k0 += 64) {
#pragma unroll
        for (int l = 0; l < 2; l++) {                        // As: 512 float4
            int lin = l * 1024 + tid * 4;
            int r = lin >> 6, k = lin & 63;
            *(float4*)&As[r][k] = *(const float4*)(X + (size_t)(m0 + r) * DINN + k0 + k);
        }
#pragma unroll
        for (int l = 0; l < 8; l++) {                        // Bs: 2048 float4
            int lin = l * 1024 + tid * 4;
            int kk = lin >> 7, n = lin & 127;
            *(float4*)&Bs[kk][n] = *(const float4*)(W + (size_t)(k0 + kk) * DOUTT + n);
        }
        __syncthreads();
#pragma unroll 2
        for (int kk4 = 0; kk4 < 16; ++kk4) {
            float4 a4[4];
#pragma unroll
            for (int r = 0; r < 4; r++)
                a4[r] = *(const float4*)&As[warp * 4 + r][kk4 * 4];
#pragma unroll
            for (int e = 0; e < 4; e++) {
                float4 b = *(const float4*)&Bs[kk4 * 4 + e][lane * 4];
                unsigned long long b01 = pack2(b.x, b.y);
                unsigned long long b23 = pack2(b.z, b.w);
#pragma unroll
                for (int r = 0; r < 4; r++) {
                    float a = (e == 0) ? a4[r].x : (e == 1) ? a4[r].y : (e == 2) ? a4[r].z : a4[r].w;
                    unsigned long long aa = pack2(a, a);
                    acc01[r] = ffma2(aa, b01, acc01[r]);
                    acc23[r] = ffma2(aa, b23, acc23[r]);
                }
            }
        }
        __syncthreads();
    }

    // epilogue: store h + fused per-row stats (s, t, E1, E2)
    float4 as4 = ((const float4*)a_self)[lane];
    float4 an4 = ((const float4*)a_neighs)[lane];
#pragma unroll
    for (int r = 0; r < 4; r++) {
        float4 v;
        unpack2(acc01[r], v.x, v.y);
        unpack2(acc23[r], v.z, v.w);
        int row = m0 + warp * 4 + r;
        *(float4*)(g_h + (size_t)row * DOUTT + lane * 4) = v;

        float s = v.x * as4.x + v.y * as4.y + v.z * as4.z + v.w * as4.w;
        float t = v.x * an4.x + v.y * an4.y + v.z * an4.z + v.w * an4.w;
#pragma unroll
        for (int o = 16; o; o >>= 1) {
            s += __shfl_xor_sync(0xffffffffu, s, o);
            t += __shfl_xor_sync(0xffffffffu, t, o);
        }
        if (lane == 0) {
            g_s[row] = s;
            g_t[row] = t;
            g_E[2 * row]     = __expf(t);
            g_E[2 * row + 1] = __expf(LALPHA * t);
        }
    }
}

// ---------------- global descending rank sort of t (stable, exact) ----------------
__global__ __launch_bounds__(256) void k_rank() {
    __shared__ float ts[NN];        // 32 KB
    __shared__ int   partial[256];
    int tid = threadIdx.x;
#pragma unroll
    for (int l = 0; l < 8; l++) {
        int lin = l * 1024 + tid * 4;
        *(float4*)&ts[lin] = *(const float4*)(g_t + lin);
    }
    __syncthreads();

    int local = tid >> 2;             // which j in this block
    int q     = tid & 3;              // interleaved quarter (conflict-free float4s)
    int j     = blockIdx.x * 64 + local;
    float tj  = ts[j];
    int cnt = 0;
#pragma unroll 4
    for (int k4 = 0; k4 < 512; ++k4) {
        int fidx = k4 * 4 + q;                 // float4 index, interleaved by quarter
        float4 v = *(const float4*)&ts[fidx * 4];
        int k = fidx * 4;
        cnt += (v.x > tj) || (v.x == tj && k     < j);
        cnt += (v.y > tj) || (v.y == tj && k + 1 < j);
        cnt += (v.z > tj) || (v.z == tj && k + 2 < j);
        cnt += (v.w > tj) || (v.w == tj && k + 3 < j);
    }
    partial[tid] = cnt;
    __syncthreads();
    if (q == 0) {
        int rank = partial[tid] + partial[tid + 1] + partial[tid + 2] + partial[tid + 3];
        g_perm[rank]    = j;
        g_tsorted[rank] = tj;
    }
}

// ---------------- main fused row kernel: 2 rows / block ----------------
__global__ __launch_bounds__(256) void k_row(const int* __restrict__ adj,
                                             const int* __restrict__ action,
                                             const int* __restrict__ bp,
                                             float* __restrict__ out) {
    __shared__ unsigned char s_nib[RPB][2048];     // adj bits, 4 per byte
    __shared__ float s_red[RPB][2][8];
    __shared__ float s_par[RPB][3];                // A, B, denom
    __shared__ int   s_info[RPB][2];               // kept count, fallback flag
    __shared__ int   s_klist[RPB][MAXK];
    __shared__ float s_wlist[RPB][MAXK];

    int tid  = threadIdx.x;
    int lane = tid & 31, warp = tid >> 5;
    int row0 = blockIdx.x * RPB;

    float si0 = g_s[row0], si1 = g_s[row0 + 1];
    float c0 = __expf(-si0), c1 = __expf(-si1);   // E1 >= c  <=>  t >= -s
    const int* a0p = adj + (size_t)row0 * NN;
    const int* a1p = a0p + NN;

    float s01 = 0.f, s02 = 0.f, s11 = 0.f, s12 = 0.f;
#pragma unroll
    for (int it = 0; it < 8; ++it) {
        int base = it * 1024 + tid * 4;
        int4 a0 = __ldcs((const int4*)(a0p + base));
        int4 a1 = __ldcs((const int4*)(a1p + base));
        float4 eA = __ldg((const float4*)(g_E + 2 * base));       // {E1,E2} of j0,j1
        float4 eB = __ldg((const float4*)(g_E + 2 * base + 4));   // {E1,E2} of j2,j3

        bool v0 = a0.x > 0, v1 = a0.y > 0, v2 = a0.z > 0, v3 = a0.w > 0;
        unsigned n0 = (v0 ? 1u : 0u) | (v1 ? 2u : 0u) | (v2 ? 4u : 0u) | (v3 ? 8u : 0u);
        s01 += (v0 && eA.x >= c0) ? eA.x : 0.f;  s02 += (v0 && eA.x < c0) ? eA.y : 0.f;
        s01 += (v1 && eA.z >= c0) ? eA.z : 0.f;  s02 += (v1 && eA.z < c0) ? eA.w : 0.f;
        s01 += (v2 && eB.x >= c0) ? eB.x : 0.f;  s02 += (v2 && eB.x < c0) ? eB.y : 0.f;
        s01 += (v3 && eB.z >= c0) ? eB.z : 0.f;  s02 += (v3 && eB.z < c0) ? eB.w : 0.f;

        bool w0 = a1.x > 0, w1 = a1.y > 0, w2 = a1.z > 0, w3 = a1.w > 0;
        unsigned n1 = (w0 ? 1u : 0u) | (w1 ? 2u : 0u) | (w2 ? 4u : 0u) | (w3 ? 8u : 0u);
        s11 += (w0 && eA.x >= c1) ? eA.x : 0.f;  s12 += (w0 && eA.x < c1) ? eA.y : 0.f;
        s11 += (w1 && eA.z >= c1) ? eA.z : 0.f;  s12 += (w1 && eA.z < c1) ? eA.w : 0.f;
        s11 += (w2 && eB.x >= c1) ? eB.x : 0.f;  s12 += (w2 && eB.x < c1) ? eB.y : 0.f;
        s11 += (w3 && eB.z >= c1) ? eB.z : 0.f;  s12 += (w3 && eB.z < c1) ? eB.w : 0.f;

        s_nib[0][it * 256 + tid] = (unsigned char)n0;
        s_nib[1][it * 256 + tid] = (unsigned char)n1;
    }
#pragma unroll
    for (int o = 16; o; o >>= 1) {
        s01 += __shfl_xor_sync(0xffffffffu, s01, o);
        s02 += __shfl_xor_sync(0xffffffffu, s02, o);
        s11 += __shfl_xor_sync(0xffffffffu, s11, o);
        s12 += __shfl_xor_sync(0xffffffffu, s12, o);
    }
    if (lane == 0) {
        s_red[0][0][warp] = s01; s_red[0][1][warp] = s02;
        s_red[1][0][warp] = s11; s_red[1][1][warp] = s12;
    }
    __syncthreads();

    if (warp < RPB) {                // warps 0,1 each own one row
        int r = warp;
        int row = row0 + r;
        float s_i  = r ? si1 : si0;
        float cthr = r ? c1 : c0;

        float S1 = (lane < 8) ? s_red[r][0][lane] : 0.f;
        float S2 = (lane < 8) ? s_red[r][1][lane] : 0.f;
#pragma unroll
        for (int o = 4; o; o >>= 1) {
            S1 += __shfl_xor_sync(0xffffffffu, S1, o);
            S2 += __shfl_xor_sync(0xffffffffu, S2, o);
        }
        S1 = __shfl_sync(0xffffffffu, S1, 0);
        S2 = __shfl_sync(0xffffffffu, S2, 0);

        // unstabilized softmax: |s+t| bounded (~30), safe in fp32
        float A = __expf(s_i);
        float B = __expf(LALPHA * s_i);
        float denom = A * S1 + B * S2;
        if (lane == 0) { s_par[r][0] = A; s_par[r][1] = B; s_par[r][2] = denom; }

        int fallback = 0;
        int c2 = 0;
        if (bp[0] != 0) {
            int target = action[row] + 1;       // keep `target` entries (plus exact ties)
            // Phase A: threshold = target-th largest valid t (sorted walk + smem bits)
            int cnt = 0, pos = 0, found = 0;
            float t_thr = 0.f;
            while (pos < NN) {
                int ridx = pos + lane;
                int j = g_perm[ridx];
                float tv = g_tsorted[ridx];
                int bit = (s_nib[r][((j >> 10) << 8) + ((j >> 2) & 255)] >> (j & 3)) & 1;
                unsigned bal = __ballot_sync(0xffffffffu, bit);
                int c = __popc(bal);
                if (cnt + c >= target) {
                    int prefx = __popc(bal & ((1u << lane) - 1));
                    int sel = bit && (cnt + prefx + 1 == target);
                    unsigned sm = __ballot_sync(0xffffffffu, sel);
                    int src = __ffs(sm) - 1;
                    t_thr = __shfl_sync(0xffffffffu, tv, src);
                    found = 1;
                    break;
                }
                cnt += c;
                pos += 32;
            }
            if (!found) fallback = 1;   // fewer valid than target -> threshold 0 -> keep all

            // Phase B: collect kept (valid & t >= t_thr) with normalized weights
            if (!fallback) {
                pos = 0;
                while (pos < NN) {
                    int ridx = pos + lane;
                    float tv = g_tsorted[ridx];
                    int j = g_perm[ridx];
                    int bit = (s_nib[r][((j >> 10) << 8) + ((j >> 2) & 255)] >> (j & 3)) & 1;
                    bool ge = (tv >= t_thr);
                    bool keep = bit && ge;
                    unsigned balk = __ballot_sync(0xffffffffu, keep);
                    int idx = c2 + __popc(balk & ((1u << lane) - 1));
                    if (keep && idx < MAXK) {
                        float e1 = __ldg(&g_E[2 * j]);
                        float e2 = __ldg(&g_E[2 * j + 1]);
                        float w = (e1 >= cthr) ? A * e1 : B * e2;
                        s_klist[r][idx] = j;
                        s_wlist[r][idx] = w / denom;
                    }
                    c2 += __popc(balk);
                    if (c2 > MAXK) break;                                      // tie explosion
                    if (__ballot_sync(0xffffffffu, ge) != 0xffffffffu) break;  // sorted: done
                    pos += 32;
                }
                if (c2 > MAXK) fallback = 1;
            }
        } else {
            fallback = 1;   // no thresholding: dense path over all valid
        }
        if (lane == 0) { s_info[r][0] = c2; s_info[r][1] = fallback; }
    }
    __syncthreads();

    // epilogue: one (row, dim) per thread
    int r = tid >> 7, d = tid & 127;
    int row = row0 + r;
    int c2 = s_info[r][0];
    int fb = s_info[r][1];
    float acc = 0.f;
    if (!fb) {
#pragma unroll 4
        for (int k = 0; k < c2; ++k)
            acc += s_wlist[r][k] * g_h[(size_t)s_klist[r][k] * DOUTT + d];
    } else {
        float A = s_par[r][0], B = s_par[r][1];
        float inv = 1.f / s_par[r][2];
        float cthr = r ? c1 : c0;
        for (int j = 0; j < NN; ++j) {
            int bit = (s_nib[r][((j >> 10) << 8) + ((j >> 2) & 255)] >> (j & 3)) & 1;
            if (bit) {
                float e1 = __ldg(&g_E[2 * j]);
                float e2 = __ldg(&g_E[2 * j + 1]);
                float w = ((e1 >= cthr) ? A * e1 : B * e2) * inv;
                acc += w * g_h[(size_t)j * DOUTT + d];
            }
        }
    }
    out[(size_t)row * DOUTT + d] = (acc > 0.f) ? acc : expm1f(acc);
}

// ---------------- launch ----------------
extern "C" void kernel_launch(void* const* d_in, const int* in_sizes, int n_in,
                              void* d_out, int out_size) {
    const float* input    = (const float*)d_in[0];
    const int*   adj      = (const int*)d_in[1];
    const int*   action   = (const int*)d_in[2];
    const float* W        = (const float*)d_in[3];
    const float* a_self   = (const float*)d_in[4];
    const float* a_neighs = (const float*)d_in[5];
    const int*   bp       = (const int*)d_in[6];
    float* out = (float*)d_out;

    k_gemm<<<NN / 32, 256>>>(input, W, a_self, a_neighs);
    k_rank<<<NN / 64, 256>>>();
    k_row<<<NN / RPB, 256>>>(adj, action, bp, out);
}

// round 6
// speedup vs baseline: 1.8529x; 1.0139x over previous
#include <cuda_runtime.h>
#include <math.h>
#include <stdint.h>

#define NN    8192
#define DINN  256
#define DOUTT 128
#define LALPHA 0.2f
#define MAXK  128
#define RPB   4          // rows per block in k_row

// ---------------- scratch (no allocation allowed) ----------------
__device__ __align__(16) float g_h[NN * DOUTT];     // h = input @ W
__device__ __align__(16) float g_s[NN];             // h @ a_self
__device__ __align__(16) float g_t[NN];             // h @ a_neighs
__device__ __align__(16) float g_E[2 * NN];         // interleaved {E1=e^t, E2=e^(a*t)}
__device__ __align__(16) float g_tsorted[NN];       // t sorted descending
__device__ __align__(16) int   g_perm[NN];          // perm[rank] = j

// ---------------- packed fp32x2 helpers ----------------
__device__ __forceinline__ unsigned long long pack2(float lo, float hi) {
    unsigned long long r;
    asm("mov.b64 %0, {%1, %2};" : "=l"(r) : "r"(__float_as_uint(lo)), "r"(__float_as_uint(hi)));
    return r;
}
__device__ __forceinline__ void unpack2(unsigned long long v, float& lo, float& hi) {
    unsigned a, b;
    asm("mov.b64 {%0, %1}, %2;" : "=r"(a), "=r"(b) : "l"(v));
    lo = __uint_as_float(a); hi = __uint_as_float(b);
}
__device__ __forceinline__ unsigned long long ffma2(unsigned long long a, unsigned long long b,
                                                    unsigned long long c) {
    unsigned long long d;
    asm("fma.rn.f32x2 %0, %1, %2, %3;" : "=l"(d) : "l"(a), "l"(b), "l"(c));
    return d;
}
// max(a.lo*b.lo, a.hi*b.hi)  -- the exp(leaky) identity
__device__ __forceinline__ float max2(unsigned long long e, unsigned long long ab) {
    unsigned long long p;
    asm("mul.rn.f32x2 %0, %1, %2;" : "=l"(p) : "l"(e), "l"(ab));
    float lo, hi; unpack2(p, lo, hi);
    return fmaxf(lo, hi);
}

__device__ __forceinline__ void cp16(uint32_t dst, const void* src) {
    asm volatile("cp.async.cg.shared.global [%0], [%1], 16;" :: "r"(dst), "l"(src));
}
__device__ __forceinline__ uint32_t sptr(const void* p) {
    return (uint32_t)__cvta_generic_to_shared(p);
}

// ---------------- h = input @ W  (M=8192, K=256, N=128) + fused stats ----------------
// M-tile 32, K-chunk 32, cp.async double-buffered. smem 40KB static.
__global__ __launch_bounds__(256) void k_gemm(const float* __restrict__ X,
                                              const float* __restrict__ W,
                                              const float* __restrict__ a_self,
                                              const float* __restrict__ a_neighs) {
    __shared__ float As[2][32][32];     // 8 KB
    __shared__ float Bs[2][32][128];    // 32 KB
    int tid  = threadIdx.x;
    int m0   = blockIdx.x * 32;
    int warp = tid >> 5;
    int lane = tid & 31;

    int ar = tid >> 3, ak = (tid & 7) * 4;          // A: 1 float4/thread/stage

    auto issue = [&](int s) {
        int k0 = s * 32, buf = s & 1;
        cp16(sptr(&As[buf][ar][ak]), X + (size_t)(m0 + ar) * DINN + k0 + ak);
#pragma unroll
        for (int l = 0; l < 4; l++) {                // B: 4 float4/thread/stage
            int idx = l * 256 + tid;
            int kk = idx >> 5, n4 = (idx & 31) * 4;
            cp16(sptr(&Bs[buf][kk][n4]), W + (size_t)(k0 + kk) * DOUTT + n4);
        }
        asm volatile("cp.async.commit_group;");
    };

    unsigned long long acc01[4], acc23[4];
#pragma unroll
    for (int r = 0; r < 4; r++) { acc01[r] = 0ull; acc23[r] = 0ull; }

    issue(0);
    issue(1);

#pragma unroll
    for (int s = 0; s < 8; s++) {
        if (s + 2 < 8) { asm volatile("cp.async.wait_group 1;"); }
        else           { asm volatile("cp.async.wait_group 0;"); }
        __syncthreads();
        int buf = s & 1;
#pragma unroll
        for (int kk4 = 0; kk4 < 8; ++kk4) {
            float4 a4[4];
#pragma unroll
            for (int r = 0; r < 4; r++)
                a4[r] = *(const float4*)&As[buf][warp * 4 + r][kk4 * 4];
#pragma unroll
            for (int e = 0; e < 4; e++) {
                float4 b = *(const float4*)&Bs[buf][kk4 * 4 + e][lane * 4];
                unsigned long long b01 = pack2(b.x, b.y);
                unsigned long long b23 = pack2(b.z, b.w);
#pragma unroll
                for (int r = 0; r < 4; r++) {
                    float a = (e == 0) ? a4[r].x : (e == 1) ? a4[r].y : (e == 2) ? a4[r].z : a4[r].w;
                    unsigned long long aa = pack2(a, a);
                    acc01[r] = ffma2(aa, b01, acc01[r]);
                    acc23[r] = ffma2(aa, b23, acc23[r]);
                }
            }
        }
        __syncthreads();
        if (s + 2 < 8) issue(s + 2);
    }

    // epilogue: store h + fused per-row stats (s, t, E1, E2)
    float4 as4 = ((const float4*)a_self)[lane];
    float4 an4 = ((const float4*)a_neighs)[lane];
#pragma unroll
    for (int r = 0; r < 4; r++) {
        float4 v;
        unpack2(acc01[r], v.x, v.y);
        unpack2(acc23[r], v.z, v.w);
        int row = m0 + warp * 4 + r;
        *(float4*)(g_h + (size_t)row * DOUTT + lane * 4) = v;

        float s = v.x * as4.x + v.y * as4.y + v.z * as4.z + v.w * as4.w;
        float t = v.x * an4.x + v.y * an4.y + v.z * an4.z + v.w * an4.w;
#pragma unroll
        for (int o = 16; o; o >>= 1) {
            s += __shfl_xor_sync(0xffffffffu, s, o);
            t += __shfl_xor_sync(0xffffffffu, t, o);
        }
        if (lane == 0) {
            g_s[row] = s;
            g_t[row] = t;
            g_E[2 * row]     = __expf(t);
            g_E[2 * row + 1] = __expf(LALPHA * t);
        }
    }
}

// ---------------- global descending rank sort of t (stable, exact) ----------------
__global__ __launch_bounds__(256) void k_rank() {
    __shared__ float ts[NN];        // 32 KB
    __shared__ int   partial[256];
    int tid = threadIdx.x;
#pragma unroll
    for (int l = 0; l < 8; l++) {
        int lin = l * 1024 + tid * 4;
        *(float4*)&ts[lin] = *(const float4*)(g_t + lin);
    }
    __syncthreads();

    int local = tid >> 2;
    int q     = tid & 3;              // interleaved quarters -> conflict-free float4s
    int j     = blockIdx.x * 64 + local;
    float tj  = ts[j];
    int cnt = 0;
#pragma unroll 4
    for (int k4 = 0; k4 < 512; ++k4) {
        int fidx = k4 * 4 + q;
        float4 v = *(const float4*)&ts[fidx * 4];
        int k = fidx * 4;
        cnt += (v.x > tj) || (v.x == tj && k     < j);
        cnt += (v.y > tj) || (v.y == tj && k + 1 < j);
        cnt += (v.z > tj) || (v.z == tj && k + 2 < j);
        cnt += (v.w > tj) || (v.w == tj && k + 3 < j);
    }
    partial[tid] = cnt;
    __syncthreads();
    if (q == 0) {
        int rank = partial[tid] + partial[tid + 1] + partial[tid + 2] + partial[tid + 3];
        g_perm[rank]    = j;
        g_tsorted[rank] = tj;
    }
}

// ---------------- main fused row kernel: 4 rows/block, max-form softmax ----------------
// exp(leaky(s_i + t_j)) == max(A_i*E1_j, B_i*E2_j), A=e^s, B=e^{0.2s}
__global__ __launch_bounds__(256) void k_row(const int* __restrict__ adj,
                                             const int* __restrict__ action,
                                             const int* __restrict__ bp,
                                             float* __restrict__ out) {
    __shared__ unsigned s_nibw[2048];              // 16 bits/word: 4 rows x 4 cols
    __shared__ float s_red[RPB][8];
    __shared__ float s_par[RPB][3];                // A, B, denom
    __shared__ int   s_info[RPB][2];               // kept count, fallback flag
    __shared__ int   s_klist[RPB][MAXK];
    __shared__ float s_wlist[RPB][MAXK];

    int tid  = threadIdx.x;
    int lane = tid & 31, warp = tid >> 5;
    int row0 = blockIdx.x * RPB;

    float Aa[RPB], Bb[RPB];
    unsigned long long AB[RPB];
#pragma unroll
    for (int r = 0; r < RPB; r++) {
        float sv = g_s[row0 + r];
        Aa[r] = __expf(sv);
        Bb[r] = __expf(LALPHA * sv);
        AB[r] = pack2(Aa[r], Bb[r]);
    }
    const int* ap = adj + (size_t)row0 * NN;

    float acc[RPB] = {0.f, 0.f, 0.f, 0.f};
#pragma unroll
    for (int it = 0; it < 8; ++it) {
        int base = it * 1024 + tid * 4;
        int4 av[RPB];
#pragma unroll
        for (int r = 0; r < RPB; r++)
            av[r] = __ldcs((const int4*)(ap + (size_t)r * NN + base));
        float4 eA = __ldg((const float4*)(g_E + 2 * base));       // {E1,E2} of j0,j1
        float4 eB = __ldg((const float4*)(g_E + 2 * base + 4));   // {E1,E2} of j2,j3
        unsigned long long e0 = pack2(eA.x, eA.y);
        unsigned long long e1 = pack2(eA.z, eA.w);
        unsigned long long e2 = pack2(eB.x, eB.y);
        unsigned long long e3 = pack2(eB.z, eB.w);

        unsigned nw = 0;
#pragma unroll
        for (int r = 0; r < RPB; r++) {
            bool v0 = av[r].x > 0, v1 = av[r].y > 0, v2 = av[r].z > 0, v3 = av[r].w > 0;
            acc[r] += v0 ? max2(e0, AB[r]) : 0.f;
            acc[r] += v1 ? max2(e1, AB[r]) : 0.f;
            acc[r] += v2 ? max2(e2, AB[r]) : 0.f;
            acc[r] += v3 ? max2(e3, AB[r]) : 0.f;
            nw |= (v0 ? 1u : 0u) << (r * 4);
            nw |= (v1 ? 2u : 0u) << (r * 4);
            nw |= (v2 ? 4u : 0u) << (r * 4);
            nw |= (v3 ? 8u : 0u) << (r * 4);
        }
        s_nibw[it * 256 + tid] = nw;
    }
#pragma unroll
    for (int r = 0; r < RPB; r++) {
#pragma unroll
        for (int o = 16; o; o >>= 1)
            acc[r] += __shfl_xor_sync(0xffffffffu, acc[r], o);
        if (lane == 0) s_red[r][warp] = acc[r];
    }
    __syncthreads();

    if (warp < RPB) {                // warps 0..3 each own one row
        int r = warp;
        int row = row0 + r;
        float A = Aa[r], B = Bb[r];
        unsigned long long ABr = AB[r];

        float S = (lane < 8) ? s_red[r][lane] : 0.f;
#pragma unroll
        for (int o = 4; o; o >>= 1)
            S += __shfl_xor_sync(0xffffffffu, S, o);
        float denom = __shfl_sync(0xffffffffu, S, 0);
        if (lane == 0) { s_par[r][0] = A; s_par[r][1] = B; s_par[r][2] = denom; }

        int fallback = 0;
        int c2 = 0;
        if (bp[0] != 0) {
            int target = action[row] + 1;       // keep `target` entries (plus exact ties)
            // Phase A: threshold = target-th largest valid t (sorted walk + smem bits)
            int cnt = 0, pos = 0, found = 0;
            float t_thr = 0.f;
            while (pos < NN) {
                int ridx = pos + lane;
                int j = g_perm[ridx];
                float tv = g_tsorted[ridx];
                int bit = (s_nibw[((j >> 10) << 8) + ((j >> 2) & 255)] >> (r * 4 + (j & 3))) & 1;
                unsigned bal = __ballot_sync(0xffffffffu, bit);
                int c = __popc(bal);
                if (cnt + c >= target) {
                    int prefx = __popc(bal & ((1u << lane) - 1));
                    int sel = bit && (cnt + prefx + 1 == target);
                    unsigned sm = __ballot_sync(0xffffffffu, sel);
                    int src = __ffs(sm) - 1;
                    t_thr = __shfl_sync(0xffffffffu, tv, src);
                    found = 1;
                    break;
                }
                cnt += c;
                pos += 32;
            }
            if (!found) fallback = 1;   // fewer valid than target -> threshold 0 -> keep all

            // Phase B: collect kept (valid & t >= t_thr) with normalized weights
            if (!fallback) {
                pos = 0;
                while (pos < NN) {
                    int ridx = pos + lane;
                    float tv = g_tsorted[ridx];
                    int j = g_perm[ridx];
                    int bit = (s_nibw[((j >> 10) << 8) + ((j >> 2) & 255)] >> (r * 4 + (j & 3))) & 1;
                    bool ge = (tv >= t_thr);
                    bool keep = bit && ge;
                    unsigned balk = __ballot_sync(0xffffffffu, keep);
                    int idx = c2 + __popc(balk & ((1u << lane) - 1));
                    if (keep && idx < MAXK) {
                        unsigned long long ep = pack2(__ldg(&g_E[2 * j]), __ldg(&g_E[2 * j + 1]));
                        s_klist[r][idx] = j;
                        s_wlist[r][idx] = max2(ep, ABr) / denom;
                    }
                    c2 += __popc(balk);
                    if (c2 > MAXK) break;                                      // tie explosion
                    if (__ballot_sync(0xffffffffu, ge) != 0xffffffffu) break;  // sorted: done
                    pos += 32;
                }
                if (c2 > MAXK) fallback = 1;
            }
        } else {
            fallback = 1;   // no thresholding: dense path over all valid
        }
        if (lane == 0) { s_info[r][0] = c2; s_info[r][1] = fallback; }
    }
    __syncthreads();

    // epilogue: each thread handles 2 (row, dim) pairs
    int d = tid & 127;
#pragma unroll
    for (int rr = 0; rr < 2; ++rr) {
        int r = (tid >> 7) + rr * 2;
        int row = row0 + r;
        int c2 = s_info[r][0];
        int fb = s_info[r][1];
        float a = 0.f;
        if (!fb) {
#pragma unroll 4
            for (int k = 0; k < c2; ++k)
                a += s_wlist[r][k] * g_h[(size_t)s_klist[r][k] * DOUTT + d];
        } else {
            unsigned long long ABr = pack2(s_par[r][0], s_par[r][1]);
            float inv = 1.f / s_par[r][2];
            for (int j = 0; j < NN; ++j) {
                int bit = (s_nibw[((j >> 10) << 8) + ((j >> 2) & 255)] >> (r * 4 + (j & 3))) & 1;
                if (bit) {
                    unsigned long long ep = pack2(__ldg(&g_E[2 * j]), __ldg(&g_E[2 * j + 1]));
                    a += max2(ep, ABr) * inv * g_h[(size_t)j * DOUTT + d];
                }
            }
        }
        out[(size_t)row * DOUTT + d] = (a > 0.f) ? a : expm1f(a);
    }
}

// ---------------- launch ----------------
extern "C" void kernel_launch(void* const* d_in, const int* in_sizes, int n_in,
                              void* d_out, int out_size) {
    const float* input    = (const float*)d_in[0];
    const int*   adj      = (const int*)d_in[1];
    const int*   action   = (const int*)d_in[2];
    const float* W        = (const float*)d_in[3];
    const float* a_self   = (const float*)d_in[4];
    const float* a_neighs = (const float*)d_in[5];
    const int*   bp       = (const int*)d_in[6];
    float* out = (float*)d_out;

    k_gemm<<<NN / 32, 256>>>(input, W, a_self, a_neighs);
    k_rank<<<NN / 64, 256>>>();
    k_row<<<NN / RPB, 256>>>(adj, action, bp, out);
}